// round 8
// baseline (speedup 1.0000x reference)
#include <cuda_runtime.h>
#include <math.h>

#define NATOMS 10000
#define NPAIR  100000

typedef unsigned long long u64;
__device__ __forceinline__ u64 pk2(float a, float b) {
    u64 r; asm("mov.b64 %0,{%1,%2};" : "=l"(r) : "f"(a), "f"(b)); return r;
}
__device__ __forceinline__ void up2(u64 v, float& a, float& b) {
    asm("mov.b64 {%0,%1},%2;" : "=f"(a), "=f"(b) : "l"(v));
}
__device__ __forceinline__ u64 fma2(u64 a, u64 b, u64 c) {
    u64 d; asm("fma.rn.f32x2 %0,%1,%2,%3;" : "=l"(d) : "l"(a), "l"(b), "l"(c)); return d;
}

// Scratch (static device allocations — allowed). 16B-aligned: accessed as float4.
__device__ __align__(16) float d_Q   [NATOMS * 384];
__device__ __align__(16) float d_Kb  [NATOMS * 384];
__device__ __align__(16) float d_P   [NATOMS * 512];
__device__ __align__(16) float d_alpha[(size_t)NPAIR * 12];
__device__ __align__(16) float d_sphp [(size_t)NPAIR * 16];   // 16-padded sph copy

// Dummy no-op kernel: shifts ncu's skip-5 capture window onto alpha_kernel.
__global__ void dummy_kernel() {}

// ---------------------------------------------------------------------------
// Fused per-atom prep. 32 atoms / 256 threads. xh lives only in smem.
// ---------------------------------------------------------------------------
__global__ __launch_bounds__(256) void prep_kernel(
    const float* __restrict__ x,    const float* __restrict__ W_in,
    const float* __restrict__ b_in,
    const float* __restrict__ WQ,   const float* __restrict__ WK,
    const float* __restrict__ W_out)
{
    __shared__ __align__(16) float sx[32][128];
    union __align__(16) UB {
        float w[32][128];
        float qk[2][2][32][36];     // [Q/K][dh parity][i][j], 36-pad
    };
    __shared__ UB sb;

    int tid  = threadIdx.x;
    int wid  = tid >> 5, lane = tid & 31;
    int a0   = blockIdx.x * 32;

    // ---- load x tile ----
#pragma unroll
    for (int t = 0; t < 4; t++) {
        int p = tid + t * 256;
        int row = p >> 5, c4 = p & 31;
        float4 v = make_float4(0.f, 0.f, 0.f, 0.f);
        if (a0 + row < NATOMS)
            v = *(const float4*)(x + (size_t)(a0 + row) * 128 + c4 * 4);
        *(float4*)&sx[row][c4 * 4] = v;
    }

    // ---- Phase 1: xh = x @ W_in + b ----
    float4 wr[4];
#pragma unroll
    for (int t = 0; t < 4; t++) {
        int p = tid + t * 256;
        wr[t] = *(const float4*)(W_in + (size_t)(p >> 5) * 128 + (p & 31) * 4);
    }
    u64 acc2[4][2];
#pragma unroll
    for (int i = 0; i < 4; i++) { acc2[i][0] = 0ull; acc2[i][1] = 0ull; }

    for (int kk = 0; kk < 128; kk += 32) {
        __syncthreads();
#pragma unroll
        for (int t = 0; t < 4; t++) {
            int p = tid + t * 256;
            *(float4*)&sb.w[p >> 5][(p & 31) * 4] = wr[t];
        }
        __syncthreads();
        if (kk < 96) {
#pragma unroll
            for (int t = 0; t < 4; t++) {
                int p = tid + t * 256;
                wr[t] = *(const float4*)(W_in + (size_t)(kk + 32 + (p >> 5)) * 128
                                         + (p & 31) * 4);
            }
        }
#pragma unroll
        for (int k4 = 0; k4 < 8; k4++) {
            float av[4][4];
#pragma unroll
            for (int i = 0; i < 4; i++) {
                float4 a4 = *(float4*)&sx[wid * 4 + i][kk + k4 * 4];
                av[i][0] = a4.x; av[i][1] = a4.y; av[i][2] = a4.z; av[i][3] = a4.w;
            }
#pragma unroll
            for (int k = 0; k < 4; k++) {
                float4 b = *(float4*)&sb.w[k4 * 4 + k][lane * 4];
                u64 b01 = pk2(b.x, b.y), b23 = pk2(b.z, b.w);
#pragma unroll
                for (int i = 0; i < 4; i++) {
                    u64 a2 = pk2(av[i][k], av[i][k]);
                    acc2[i][0] = fma2(a2, b01, acc2[i][0]);
                    acc2[i][1] = fma2(a2, b23, acc2[i][1]);
                }
            }
        }
    }
    __syncwarp();   // warp reads/writes only its own 4 rows
    {
        float4 bb = *(const float4*)(b_in + lane * 4);
#pragma unroll
        for (int i = 0; i < 4; i++) {
            float v0, v1, v2, v3;
            up2(acc2[i][0], v0, v1);
            up2(acc2[i][1], v2, v3);
            float4 v = make_float4(v0 + bb.x, v1 + bb.y, v2 + bb.z, v3 + bb.w);
            *(float4*)&sx[wid * 4 + i][lane * 4] = v;
        }
    }
    __syncwarp();

    // ---- Phase 2: Q,K — 6 rounds of 2 dh ----
    float4 qr[4];
#pragma unroll
    for (int t = 0; t < 4; t++) {
        int e = (tid + t * 256) * 4;
        const float* src = (e >> 11) ? WK : WQ;
        int rem = e & 2047;
        qr[t] = *(const float4*)(src + (rem >> 10) * 1024 + (rem & 1023));
    }
    for (int r = 0; r < 6; r++) {
        __syncthreads();
#pragma unroll
        for (int t = 0; t < 4; t++) {
            int e = (tid + t * 256) * 4;
            int sel = e >> 11, rem = e & 2047;
            int dhp = rem >> 10, w = rem & 1023;
            *(float4*)&sb.qk[sel][dhp][w >> 5][w & 31] = qr[t];
        }
        __syncthreads();
        if (r < 5) {
#pragma unroll
            for (int t = 0; t < 4; t++) {
                int e = (tid + t * 256) * 4;
                const float* src = (e >> 11) ? WK : WQ;
                int rem = e & 2047;
                qr[t] = *(const float4*)(src + (size_t)(2 * (r + 1) + (rem >> 10)) * 1024
                                         + (rem & 1023));
            }
        }
#pragma unroll
        for (int u = 0; u < 2; u++) {
            int dh = 2 * r + u, h = dh & 3;
            u64 qa2[4] = {0ull, 0ull, 0ull, 0ull};
            u64 ka2[4] = {0ull, 0ull, 0ull, 0ull};
#pragma unroll
            for (int j4 = 0; j4 < 8; j4++) {
                float4 wq = *(float4*)&sb.qk[0][u][lane][j4 * 4];
                float4 wk = *(float4*)&sb.qk[1][u][lane][j4 * 4];
                u64 wq01 = pk2(wq.x, wq.y), wq23 = pk2(wq.z, wq.w);
                u64 wk01 = pk2(wk.x, wk.y), wk23 = pk2(wk.z, wk.w);
#pragma unroll
                for (int rr = 0; rr < 4; rr++) {
                    float4 xv = *(float4*)&sx[wid * 4 + rr][h * 32 + j4 * 4];
                    u64 x01 = pk2(xv.x, xv.y), x23 = pk2(xv.z, xv.w);
                    qa2[rr] = fma2(x01, wq01, qa2[rr]);
                    qa2[rr] = fma2(x23, wq23, qa2[rr]);
                    ka2[rr] = fma2(x01, wk01, ka2[rr]);
                    ka2[rr] = fma2(x23, wk23, ka2[rr]);
                }
            }
#pragma unroll
            for (int rr = 0; rr < 4; rr++) {
                int a = a0 + wid * 4 + rr;
                if (a < NATOMS) {
                    float qlo, qhi, klo, khi;
                    up2(qa2[rr], qlo, qhi);
                    up2(ka2[rr], klo, khi);
                    d_Q [(size_t)a * 384 + dh * 32 + lane] = qlo + qhi;
                    d_Kb[(size_t)a * 384 + dh * 32 + lane] = klo + khi;
                }
            }
        }
    }

    // ---- Phase 3: P = xh_head @ W_out block, per head ----
    float4 pr[4];
#pragma unroll
    for (int t = 0; t < 4; t++) {
        int p = tid + t * 256;
        pr[t] = *(const float4*)(W_out + (size_t)(p >> 5) * 128 + (p & 31) * 4);
    }
    for (int h = 0; h < 4; h++) {
        __syncthreads();
#pragma unroll
        for (int t = 0; t < 4; t++) {
            int p = tid + t * 256;
            *(float4*)&sb.w[p >> 5][(p & 31) * 4] = pr[t];
        }
        __syncthreads();
        if (h < 3) {
#pragma unroll
            for (int t = 0; t < 4; t++) {
                int p = tid + t * 256;
                pr[t] = *(const float4*)(W_out + (size_t)((h + 1) * 32 + (p >> 5)) * 128
                                         + (p & 31) * 4);
            }
        }
        u64 pa2[4][2];
#pragma unroll
        for (int i = 0; i < 4; i++) { pa2[i][0] = 0ull; pa2[i][1] = 0ull; }
#pragma unroll
        for (int k4 = 0; k4 < 8; k4++) {
            float av[4][4];
#pragma unroll
            for (int i = 0; i < 4; i++) {
                float4 a4 = *(float4*)&sx[wid * 4 + i][h * 32 + k4 * 4];
                av[i][0] = a4.x; av[i][1] = a4.y; av[i][2] = a4.z; av[i][3] = a4.w;
            }
#pragma unroll
            for (int k = 0; k < 4; k++) {
                float4 b = *(float4*)&sb.w[k4 * 4 + k][lane * 4];
                u64 b01 = pk2(b.x, b.y), b23 = pk2(b.z, b.w);
#pragma unroll
                for (int i = 0; i < 4; i++) {
                    u64 a2 = pk2(av[i][k], av[i][k]);
                    pa2[i][0] = fma2(a2, b01, pa2[i][0]);
                    pa2[i][1] = fma2(a2, b23, pa2[i][1]);
                }
            }
        }
#pragma unroll
        for (int i = 0; i < 4; i++) {
            int a = a0 + wid * 4 + i;
            if (a < NATOMS) {
                float v0, v1, v2, v3;
                up2(pa2[i][0], v0, v1);
                up2(pa2[i][1], v2, v3);
                *(float4*)&d_P[(size_t)a * 512 + h * 128 + lane * 4] =
                    make_float4(v0, v1, v2, v3);
            }
        }
    }
}

// ---------------------------------------------------------------------------
// alpha: R3-proven scalar form. e = Q_i*K_j hoisted before the wacc loop;
// scalar FFMA wacc; (256,2) bounds. Emits 16-padded sph copy for agg.
// ---------------------------------------------------------------------------
__global__ __launch_bounds__(256, 2) void alpha_kernel(
    const float* __restrict__ rbf,  const float* __restrict__ phi,
    const float* __restrict__ pmask,
    const int*   __restrict__ idx_i, const int* __restrict__ idx_j,
    const float* __restrict__ Wf1,  const float* __restrict__ bf1,
    const float* __restrict__ Wf2,  const float* __restrict__ bf2,
    const float* __restrict__ sph)
{
    __shared__ __align__(16) float sW[32 * 384];   // [k][lane][12]
    __shared__ __align__(16) float sWf1[32][33];
    int tid = threadIdx.x;
    for (int idx = tid; idx < 32 * 384; idx += 256) {
        int k = idx / 384, f = idx - k * 384;
        sW[k * 384 + (f & 31) * 12 + (f >> 5)] = Wf2[idx];
    }
    for (int t = tid; t < 1024; t += 256) sWf1[t >> 5][t & 31] = Wf1[t];
    int lane = tid & 31;
    float bf1v = bf1[lane];
    float bf2v[12];
#pragma unroll
    for (int d = 0; d < 12; d++) bf2v[d] = bf2[d * 32 + lane];
    __syncthreads();

    int warp  = blockIdx.x * 8 + (tid >> 5);
    int nwarp = gridDim.x * 8;

    for (int pb = warp * 4; pb < NPAIR; pb += nwarp * 4) {
        // ---- sph padded copy for agg ----
#pragma unroll
        for (int t = lane; t < 60; t += 32) {
            int qq = t / 15, mm = t - qq * 15;
            d_sphp[(size_t)(pb + qq) * 16 + mm] = sph[(size_t)pb * 15 + t];
        }
        // ---- hoisted gathers: e[q][d] = Q_i * K_j ----
        float e[4][12], scale[4];
#pragma unroll
        for (int q = 0; q < 4; q++) {
            int p  = pb + q;
            int ii = idx_i[p], jj = idx_j[p];
            const float* Qr = &d_Q [(size_t)ii * 384 + lane];
            const float* Kr = &d_Kb[(size_t)jj * 384 + lane];
#pragma unroll
            for (int d = 0; d < 12; d++)
                e[q][d] = Qr[d * 32] * Kr[d * 32];
            float m = pmask[p];
            scale[q] = phi[p] * m * m * m * 0.17677669529663687f;
        }
        // ---- h1 for 4 pairs (lane k owns h1[k]) ----
        float h1[4];
#pragma unroll
        for (int q = 0; q < 4; q++) {
            float rv = rbf[(size_t)(pb + q) * 32 + lane];
            float t = bf1v;
#pragma unroll
            for (int r = 0; r < 32; r++)
                t += __shfl_sync(0xffffffffu, rv, r) * sWf1[r][lane];
            float sp = (t > 20.f) ? t : log1pf(expf(t));
            h1[q] = sp - 0.69314718055994531f;
        }
        // ---- Wij accumulation (scalar) ----
        float wacc[4][12];
#pragma unroll
        for (int q = 0; q < 4; q++)
#pragma unroll
            for (int d = 0; d < 12; d++) wacc[q][d] = bf2v[d];

#pragma unroll 4
        for (int k = 0; k < 32; k++) {
            const float4* wp = (const float4*)&sW[k * 384 + lane * 12];
            float4 w0 = wp[0], w1 = wp[1], w2 = wp[2];
#pragma unroll
            for (int q = 0; q < 4; q++) {
                float hk = __shfl_sync(0xffffffffu, h1[q], k);
                wacc[q][0]  += hk * w0.x; wacc[q][1]  += hk * w0.y;
                wacc[q][2]  += hk * w0.z; wacc[q][3]  += hk * w0.w;
                wacc[q][4]  += hk * w1.x; wacc[q][5]  += hk * w1.y;
                wacc[q][6]  += hk * w1.z; wacc[q][7]  += hk * w1.w;
                wacc[q][8]  += hk * w2.x; wacc[q][9]  += hk * w2.y;
                wacc[q][10] += hk * w2.z; wacc[q][11] += hk * w2.w;
            }
        }
        // ---- alpha = reduce_lane e*wacc, scaled ----
#pragma unroll
        for (int q = 0; q < 4; q++) {
            float my = 0.f;
#pragma unroll
            for (int d = 0; d < 12; d++) {
                float partial = e[q][d] * wacc[q][d];
#pragma unroll
                for (int o = 16; o > 0; o >>= 1)
                    partial += __shfl_xor_sync(0xffffffffu, partial, o);
                if (lane == d) my = partial * scale[q];
            }
            if (lane < 12) d_alpha[(size_t)(pb + q) * 12 + lane] = my;
        }
    }
}

// ---------------------------------------------------------------------------
// agg: each warp owns every 4th pair for ALL 128 channels (lane = 4 chans),
// zero syncs in the pair loop; one smem combine at the end.
// ---------------------------------------------------------------------------
__global__ __launch_bounds__(128) void agg_kernel(
    const int*   __restrict__ idx_i, const int* __restrict__ idx_j,
    const float* __restrict__ b_out, float* __restrict__ out)
{
    int atom = blockIdx.x;
    int tid  = threadIdx.x;
    int wid  = tid >> 5, lane = tid & 31;
    __shared__ int srange[2];
    __shared__ __align__(16) float sacc[4][15][132];

    if (tid < 2) {
        int target = atom + tid;
        int lo = 0, hi = NPAIR;
        while (lo < hi) {
            int mid = (lo + hi) >> 1;
            if (idx_i[mid] < target) lo = mid + 1; else hi = mid;
        }
        srange[tid] = lo;
    }
    __syncthreads();
    int p0 = srange[0], p1 = srange[1];

    const int DEGM[15] = {0,0,0, 1,1,1,1,1, 2,2,2,2,2,2,2};

    float acc[15][4];
#pragma unroll
    for (int m = 0; m < 15; m++)
#pragma unroll
        for (int cc = 0; cc < 4; cc++) acc[m][cc] = 0.f;

    for (int p = p0 + wid; p < p1; p += 4) {
        int j = idx_j[p];
        const float4* alp = (const float4*)(d_alpha + (size_t)p * 12);
        float4 A0 = alp[0], A1 = alp[1], A2 = alp[2];
        const float4* spp = (const float4*)(d_sphp + (size_t)p * 16);
        float4 S0 = spp[0], S1 = spp[1], S2 = spp[2], S3 = spp[3];
        const float4* Pr = (const float4*)(d_P + (size_t)j * 512) + lane;
        float4 P0 = Pr[0], P1 = Pr[32], P2 = Pr[64], P3 = Pr[96];

        float al[3][4] = {{A0.x,A0.y,A0.z,A0.w},
                          {A1.x,A1.y,A1.z,A1.w},
                          {A2.x,A2.y,A2.z,A2.w}};
        float pv[4][4] = {{P0.x,P0.y,P0.z,P0.w},
                          {P1.x,P1.y,P1.z,P1.w},
                          {P2.x,P2.y,P2.z,P2.w},
                          {P3.x,P3.y,P3.z,P3.w}};
        float sp[15] = {S0.x,S0.y,S0.z,S0.w, S1.x,S1.y,S1.z,S1.w,
                        S2.x,S2.y,S2.z,S2.w, S3.x,S3.y,S3.z};

        float ee[3][4];
#pragma unroll
        for (int d = 0; d < 3; d++)
#pragma unroll
            for (int cc = 0; cc < 4; cc++)
                ee[d][cc] = al[d][0]*pv[0][cc] + al[d][1]*pv[1][cc]
                          + al[d][2]*pv[2][cc] + al[d][3]*pv[3][cc];
#pragma unroll
        for (int m = 0; m < 15; m++) {
            int dg = DEGM[m];
#pragma unroll
            for (int cc = 0; cc < 4; cc++)
                acc[m][cc] += sp[m] * ee[dg][cc];
        }
    }

#pragma unroll
    for (int m = 0; m < 15; m++)
        *(float4*)&sacc[wid][m][lane * 4] =
            make_float4(acc[m][0], acc[m][1], acc[m][2], acc[m][3]);
    __syncthreads();

    int c = tid;
    float bo = b_out[c];
#pragma unroll
    for (int m = 0; m < 15; m++) {
        float v = sacc[0][m][c] + sacc[1][m][c] + sacc[2][m][c] + sacc[3][m][c];
        out[((size_t)atom * 15 + m) * 128 + c] = v + bo;
    }
}

// ---------------------------------------------------------------------------
extern "C" void kernel_launch(void* const* d_in, const int* in_sizes, int n_in,
                              void* d_out, int out_size)
{
    const float* x     = (const float*)d_in[0];
    const float* rbf   = (const float*)d_in[1];
    const float* sph   = (const float*)d_in[2];
    const float* phi   = (const float*)d_in[3];
    const int*   idx_i = (const int*)  d_in[4];
    const int*   idx_j = (const int*)  d_in[5];
    const float* pmask = (const float*)d_in[6];
    const float* WQ    = (const float*)d_in[7];
    const float* WK    = (const float*)d_in[8];
    const float* W_in  = (const float*)d_in[9];
    const float* b_in  = (const float*)d_in[10];
    const float* Wf1   = (const float*)d_in[11];
    const float* bf1   = (const float*)d_in[12];
    const float* Wf2   = (const float*)d_in[13];
    const float* bf2   = (const float*)d_in[14];
    const float* W_out = (const float*)d_in[15];
    const float* b_out = (const float*)d_in[16];
    float* out = (float*)d_out;

    // Two dummies shift ncu's skip-5 single-kernel capture onto alpha_kernel.
    dummy_kernel<<<1, 32>>>();
    dummy_kernel<<<1, 32>>>();
    prep_kernel<<<(NATOMS + 31) / 32, 256>>>(x, W_in, b_in, WQ, WK, W_out);
    alpha_kernel<<<296, 256>>>(rbf, phi, pmask, idx_i, idx_j,
                               Wf1, bf1, Wf2, bf2, sph);
    agg_kernel<<<NATOMS, 128>>>(idx_i, idx_j, b_out, out);
}

// round 9
// speedup vs baseline: 1.1413x; 1.1413x over previous
#include <cuda_runtime.h>
#include <math.h>

#define NATOMS 10000
#define NPAIR  100000

typedef unsigned long long u64;
__device__ __forceinline__ u64 pk2(float a, float b) {
    u64 r; asm("mov.b64 %0,{%1,%2};" : "=l"(r) : "f"(a), "f"(b)); return r;
}
__device__ __forceinline__ void up2(u64 v, float& a, float& b) {
    asm("mov.b64 {%0,%1},%2;" : "=f"(a), "=f"(b) : "l"(v));
}
__device__ __forceinline__ u64 fma2(u64 a, u64 b, u64 c) {
    u64 d; asm("fma.rn.f32x2 %0,%1,%2,%3;" : "=l"(d) : "l"(a), "l"(b), "l"(c)); return d;
}

// Scratch (static device allocations — allowed). 16B-aligned: accessed as float4.
__device__ __align__(16) float d_Q   [NATOMS * 384];
__device__ __align__(16) float d_Kb  [NATOMS * 384];
__device__ __align__(16) float d_P   [NATOMS * 512];
__device__ __align__(16) float d_alpha[(size_t)NPAIR * 12];
__device__ __align__(16) float d_sphp [(size_t)NPAIR * 16];   // 16-padded sph copy

// One dummy: shifts ncu's capture window onto agg_kernel this round.
__global__ void dummy_kernel() {}

// ---------------------------------------------------------------------------
// Fused per-atom prep. 32 atoms / 256 threads. xh lives only in smem.
// ---------------------------------------------------------------------------
__global__ __launch_bounds__(256) void prep_kernel(
    const float* __restrict__ x,    const float* __restrict__ W_in,
    const float* __restrict__ b_in,
    const float* __restrict__ WQ,   const float* __restrict__ WK,
    const float* __restrict__ W_out)
{
    __shared__ __align__(16) float sx[32][128];
    union __align__(16) UB {
        float w[32][128];
        float qk[2][2][32][36];
    };
    __shared__ UB sb;

    int tid  = threadIdx.x;
    int wid  = tid >> 5, lane = tid & 31;
    int a0   = blockIdx.x * 32;

#pragma unroll
    for (int t = 0; t < 4; t++) {
        int p = tid + t * 256;
        int row = p >> 5, c4 = p & 31;
        float4 v = make_float4(0.f, 0.f, 0.f, 0.f);
        if (a0 + row < NATOMS)
            v = *(const float4*)(x + (size_t)(a0 + row) * 128 + c4 * 4);
        *(float4*)&sx[row][c4 * 4] = v;
    }

    // ---- Phase 1: xh = x @ W_in + b ----
    float4 wr[4];
#pragma unroll
    for (int t = 0; t < 4; t++) {
        int p = tid + t * 256;
        wr[t] = *(const float4*)(W_in + (size_t)(p >> 5) * 128 + (p & 31) * 4);
    }
    u64 acc2[4][2];
#pragma unroll
    for (int i = 0; i < 4; i++) { acc2[i][0] = 0ull; acc2[i][1] = 0ull; }

    for (int kk = 0; kk < 128; kk += 32) {
        __syncthreads();
#pragma unroll
        for (int t = 0; t < 4; t++) {
            int p = tid + t * 256;
            *(float4*)&sb.w[p >> 5][(p & 31) * 4] = wr[t];
        }
        __syncthreads();
        if (kk < 96) {
#pragma unroll
            for (int t = 0; t < 4; t++) {
                int p = tid + t * 256;
                wr[t] = *(const float4*)(W_in + (size_t)(kk + 32 + (p >> 5)) * 128
                                         + (p & 31) * 4);
            }
        }
#pragma unroll
        for (int k4 = 0; k4 < 8; k4++) {
            float av[4][4];
#pragma unroll
            for (int i = 0; i < 4; i++) {
                float4 a4 = *(float4*)&sx[wid * 4 + i][kk + k4 * 4];
                av[i][0] = a4.x; av[i][1] = a4.y; av[i][2] = a4.z; av[i][3] = a4.w;
            }
#pragma unroll
            for (int k = 0; k < 4; k++) {
                float4 b = *(float4*)&sb.w[k4 * 4 + k][lane * 4];
                u64 b01 = pk2(b.x, b.y), b23 = pk2(b.z, b.w);
#pragma unroll
                for (int i = 0; i < 4; i++) {
                    u64 a2 = pk2(av[i][k], av[i][k]);
                    acc2[i][0] = fma2(a2, b01, acc2[i][0]);
                    acc2[i][1] = fma2(a2, b23, acc2[i][1]);
                }
            }
        }
    }
    __syncwarp();
    {
        float4 bb = *(const float4*)(b_in + lane * 4);
#pragma unroll
        for (int i = 0; i < 4; i++) {
            float v0, v1, v2, v3;
            up2(acc2[i][0], v0, v1);
            up2(acc2[i][1], v2, v3);
            float4 v = make_float4(v0 + bb.x, v1 + bb.y, v2 + bb.z, v3 + bb.w);
            *(float4*)&sx[wid * 4 + i][lane * 4] = v;
        }
    }
    __syncwarp();

    // ---- Phase 2: Q,K — 6 rounds of 2 dh ----
    float4 qr[4];
#pragma unroll
    for (int t = 0; t < 4; t++) {
        int e = (tid + t * 256) * 4;
        const float* src = (e >> 11) ? WK : WQ;
        int rem = e & 2047;
        qr[t] = *(const float4*)(src + (rem >> 10) * 1024 + (rem & 1023));
    }
    for (int r = 0; r < 6; r++) {
        __syncthreads();
#pragma unroll
        for (int t = 0; t < 4; t++) {
            int e = (tid + t * 256) * 4;
            int sel = e >> 11, rem = e & 2047;
            int dhp = rem >> 10, w = rem & 1023;
            *(float4*)&sb.qk[sel][dhp][w >> 5][w & 31] = qr[t];
        }
        __syncthreads();
        if (r < 5) {
#pragma unroll
            for (int t = 0; t < 4; t++) {
                int e = (tid + t * 256) * 4;
                const float* src = (e >> 11) ? WK : WQ;
                int rem = e & 2047;
                qr[t] = *(const float4*)(src + (size_t)(2 * (r + 1) + (rem >> 10)) * 1024
                                         + (rem & 1023));
            }
        }
#pragma unroll
        for (int u = 0; u < 2; u++) {
            int dh = 2 * r + u, h = dh & 3;
            u64 qa2[4] = {0ull, 0ull, 0ull, 0ull};
            u64 ka2[4] = {0ull, 0ull, 0ull, 0ull};
#pragma unroll
            for (int j4 = 0; j4 < 8; j4++) {
                float4 wq = *(float4*)&sb.qk[0][u][lane][j4 * 4];
                float4 wk = *(float4*)&sb.qk[1][u][lane][j4 * 4];
                u64 wq01 = pk2(wq.x, wq.y), wq23 = pk2(wq.z, wq.w);
                u64 wk01 = pk2(wk.x, wk.y), wk23 = pk2(wk.z, wk.w);
#pragma unroll
                for (int rr = 0; rr < 4; rr++) {
                    float4 xv = *(float4*)&sx[wid * 4 + rr][h * 32 + j4 * 4];
                    u64 x01 = pk2(xv.x, xv.y), x23 = pk2(xv.z, xv.w);
                    qa2[rr] = fma2(x01, wq01, qa2[rr]);
                    qa2[rr] = fma2(x23, wq23, qa2[rr]);
                    ka2[rr] = fma2(x01, wk01, ka2[rr]);
                    ka2[rr] = fma2(x23, wk23, ka2[rr]);
                }
            }
#pragma unroll
            for (int rr = 0; rr < 4; rr++) {
                int a = a0 + wid * 4 + rr;
                if (a < NATOMS) {
                    float qlo, qhi, klo, khi;
                    up2(qa2[rr], qlo, qhi);
                    up2(ka2[rr], klo, khi);
                    d_Q [(size_t)a * 384 + dh * 32 + lane] = qlo + qhi;
                    d_Kb[(size_t)a * 384 + dh * 32 + lane] = klo + khi;
                }
            }
        }
    }

    // ---- Phase 3: P = xh_head @ W_out block, per head ----
    float4 pr[4];
#pragma unroll
    for (int t = 0; t < 4; t++) {
        int p = tid + t * 256;
        pr[t] = *(const float4*)(W_out + (size_t)(p >> 5) * 128 + (p & 31) * 4);
    }
    for (int h = 0; h < 4; h++) {
        __syncthreads();
#pragma unroll
        for (int t = 0; t < 4; t++) {
            int p = tid + t * 256;
            *(float4*)&sb.w[p >> 5][(p & 31) * 4] = pr[t];
        }
        __syncthreads();
        if (h < 3) {
#pragma unroll
            for (int t = 0; t < 4; t++) {
                int p = tid + t * 256;
                pr[t] = *(const float4*)(W_out + (size_t)((h + 1) * 32 + (p >> 5)) * 128
                                         + (p & 31) * 4);
            }
        }
        u64 pa2[4][2];
#pragma unroll
        for (int i = 0; i < 4; i++) { pa2[i][0] = 0ull; pa2[i][1] = 0ull; }
#pragma unroll
        for (int k4 = 0; k4 < 8; k4++) {
            float av[4][4];
#pragma unroll
            for (int i = 0; i < 4; i++) {
                float4 a4 = *(float4*)&sx[wid * 4 + i][h * 32 + k4 * 4];
                av[i][0] = a4.x; av[i][1] = a4.y; av[i][2] = a4.z; av[i][3] = a4.w;
            }
#pragma unroll
            for (int k = 0; k < 4; k++) {
                float4 b = *(float4*)&sb.w[k4 * 4 + k][lane * 4];
                u64 b01 = pk2(b.x, b.y), b23 = pk2(b.z, b.w);
#pragma unroll
                for (int i = 0; i < 4; i++) {
                    u64 a2 = pk2(av[i][k], av[i][k]);
                    pa2[i][0] = fma2(a2, b01, pa2[i][0]);
                    pa2[i][1] = fma2(a2, b23, pa2[i][1]);
                }
            }
        }
#pragma unroll
        for (int i = 0; i < 4; i++) {
            int a = a0 + wid * 4 + i;
            if (a < NATOMS) {
                float v0, v1, v2, v3;
                up2(pa2[i][0], v0, v1);
                up2(pa2[i][1], v2, v3);
                *(float4*)&d_P[(size_t)a * 512 + h * 128 + lane * 4] =
                    make_float4(v0, v1, v2, v3);
            }
        }
    }
}

// ---------------------------------------------------------------------------
// alpha: R8 scalar form (e hoisted, scalar wacc, (256,2)). Unchanged.
// ---------------------------------------------------------------------------
__global__ __launch_bounds__(256, 2) void alpha_kernel(
    const float* __restrict__ rbf,  const float* __restrict__ phi,
    const float* __restrict__ pmask,
    const int*   __restrict__ idx_i, const int* __restrict__ idx_j,
    const float* __restrict__ Wf1,  const float* __restrict__ bf1,
    const float* __restrict__ Wf2,  const float* __restrict__ bf2,
    const float* __restrict__ sph)
{
    __shared__ __align__(16) float sW[32 * 384];   // [k][lane][12]
    __shared__ __align__(16) float sWf1[32][33];
    int tid = threadIdx.x;
    for (int idx = tid; idx < 32 * 384; idx += 256) {
        int k = idx / 384, f = idx - k * 384;
        sW[k * 384 + (f & 31) * 12 + (f >> 5)] = Wf2[idx];
    }
    for (int t = tid; t < 1024; t += 256) sWf1[t >> 5][t & 31] = Wf1[t];
    int lane = tid & 31;
    float bf1v = bf1[lane];
    float bf2v[12];
#pragma unroll
    for (int d = 0; d < 12; d++) bf2v[d] = bf2[d * 32 + lane];
    __syncthreads();

    int warp  = blockIdx.x * 8 + (tid >> 5);
    int nwarp = gridDim.x * 8;

    for (int pb = warp * 4; pb < NPAIR; pb += nwarp * 4) {
#pragma unroll
        for (int t = lane; t < 60; t += 32) {
            int qq = t / 15, mm = t - qq * 15;
            d_sphp[(size_t)(pb + qq) * 16 + mm] = sph[(size_t)pb * 15 + t];
        }
        float e[4][12], scale[4];
#pragma unroll
        for (int q = 0; q < 4; q++) {
            int p  = pb + q;
            int ii = idx_i[p], jj = idx_j[p];
            const float* Qr = &d_Q [(size_t)ii * 384 + lane];
            const float* Kr = &d_Kb[(size_t)jj * 384 + lane];
#pragma unroll
            for (int d = 0; d < 12; d++)
                e[q][d] = Qr[d * 32] * Kr[d * 32];
            float m = pmask[p];
            scale[q] = phi[p] * m * m * m * 0.17677669529663687f;
        }
        float h1[4];
#pragma unroll
        for (int q = 0; q < 4; q++) {
            float rv = rbf[(size_t)(pb + q) * 32 + lane];
            float t = bf1v;
#pragma unroll
            for (int r = 0; r < 32; r++)
                t += __shfl_sync(0xffffffffu, rv, r) * sWf1[r][lane];
            float sp = (t > 20.f) ? t : log1pf(expf(t));
            h1[q] = sp - 0.69314718055994531f;
        }
        float wacc[4][12];
#pragma unroll
        for (int q = 0; q < 4; q++)
#pragma unroll
            for (int d = 0; d < 12; d++) wacc[q][d] = bf2v[d];

#pragma unroll 4
        for (int k = 0; k < 32; k++) {
            const float4* wp = (const float4*)&sW[k * 384 + lane * 12];
            float4 w0 = wp[0], w1 = wp[1], w2 = wp[2];
#pragma unroll
            for (int q = 0; q < 4; q++) {
                float hk = __shfl_sync(0xffffffffu, h1[q], k);
                wacc[q][0]  += hk * w0.x; wacc[q][1]  += hk * w0.y;
                wacc[q][2]  += hk * w0.z; wacc[q][3]  += hk * w0.w;
                wacc[q][4]  += hk * w1.x; wacc[q][5]  += hk * w1.y;
                wacc[q][6]  += hk * w1.z; wacc[q][7]  += hk * w1.w;
                wacc[q][8]  += hk * w2.x; wacc[q][9]  += hk * w2.y;
                wacc[q][10] += hk * w2.z; wacc[q][11] += hk * w2.w;
            }
        }
#pragma unroll
        for (int q = 0; q < 4; q++) {
            float my = 0.f;
#pragma unroll
            for (int d = 0; d < 12; d++) {
                float partial = e[q][d] * wacc[q][d];
#pragma unroll
                for (int o = 16; o > 0; o >>= 1)
                    partial += __shfl_xor_sync(0xffffffffu, partial, o);
                if (lane == d) my = partial * scale[q];
            }
            if (lane < 12) d_alpha[(size_t)(pb + q) * 12 + lane] = my;
        }
    }
}

// ---------------------------------------------------------------------------
// agg v3: 8 atoms per block (grid 1250). Two binary searches amortized over
// ~80 pairs; double-buffered (alpha, sph) staging; P-row + idx prefetched in
// registers; atom-boundary flush driven by uniform idx_i reads.
// ---------------------------------------------------------------------------
#define APB 8
__global__ __launch_bounds__(128) void agg_kernel(
    const int*   __restrict__ idx_i, const int* __restrict__ idx_j,
    const float* __restrict__ b_out, float* __restrict__ out)
{
    int a0  = blockIdx.x * APB;
    int c   = threadIdx.x;   // 0..127 = channel
    __shared__ int srange[2];
    __shared__ float sal[2][12];
    __shared__ float ssph[2][16];

    if (c < 2) {
        int target = a0 + c * APB;
        int lo = 0, hi = NPAIR;
        while (lo < hi) {
            int mid = (lo + hi) >> 1;
            if (idx_i[mid] < target) lo = mid + 1; else hi = mid;
        }
        srange[c] = lo;
    }
    __syncthreads();
    int p0 = srange[0], p1 = srange[1];

    float bo = b_out[c];
    float acc[15];
#pragma unroll
    for (int m = 0; m < 15; m++) acc[m] = 0.f;
    int cur = a0;

    float pv0 = 0.f, pv1 = 0.f, pv2 = 0.f, pv3 = 0.f;
    int av = a0;
    if (p0 < p1) {
        int j0 = idx_j[p0];
        av = idx_i[p0];
        const float* Pr = &d_P[(size_t)j0 * 512 + c];
        pv0 = Pr[0]; pv1 = Pr[128]; pv2 = Pr[256]; pv3 = Pr[384];
        if (c < 12)                 sal[0][c]     = d_alpha[(size_t)p0 * 12 + c];
        else if (c >= 32 && c < 47) ssph[0][c-32] = d_sphp[(size_t)p0 * 16 + (c - 32)];
    }
    __syncthreads();

    for (int p = p0; p < p1; p++) {
        int b  = (p - p0) & 1;
        int nb = b ^ 1;
        // prefetch next pair
        int an = av, jn = 0;
        if (p + 1 < p1) {
            if (c < 12)                 sal[nb][c]     = d_alpha[(size_t)(p+1) * 12 + c];
            else if (c >= 32 && c < 47) ssph[nb][c-32] = d_sphp[(size_t)(p+1) * 16 + (c - 32)];
            jn = idx_j[p + 1];
            an = idx_i[p + 1];
        }
        const float* Pn = &d_P[(size_t)jn * 512 + c];
        float n0 = Pn[0], n1 = Pn[128], n2 = Pn[256], n3 = Pn[384];

        if (av != cur) {   // uniform: flush finished atoms
#pragma unroll
            for (int m = 0; m < 15; m++)
                out[((size_t)cur * 15 + m) * 128 + c] = acc[m] + bo;
            for (int a = cur + 1; a < av; a++)
#pragma unroll
                for (int m = 0; m < 15; m++)
                    out[((size_t)a * 15 + m) * 128 + c] = bo;
            cur = av;
#pragma unroll
            for (int m = 0; m < 15; m++) acc[m] = 0.f;
        }

        float e0 = sal[b][0]*pv0 + sal[b][1]*pv1 + sal[b][2] *pv2 + sal[b][3] *pv3;
        float e1 = sal[b][4]*pv0 + sal[b][5]*pv1 + sal[b][6] *pv2 + sal[b][7] *pv3;
        float e2 = sal[b][8]*pv0 + sal[b][9]*pv1 + sal[b][10]*pv2 + sal[b][11]*pv3;
        acc[0]  += ssph[b][0]  * e0;
        acc[1]  += ssph[b][1]  * e0;
        acc[2]  += ssph[b][2]  * e0;
        acc[3]  += ssph[b][3]  * e1;
        acc[4]  += ssph[b][4]  * e1;
        acc[5]  += ssph[b][5]  * e1;
        acc[6]  += ssph[b][6]  * e1;
        acc[7]  += ssph[b][7]  * e1;
        acc[8]  += ssph[b][8]  * e2;
        acc[9]  += ssph[b][9]  * e2;
        acc[10] += ssph[b][10] * e2;
        acc[11] += ssph[b][11] * e2;
        acc[12] += ssph[b][12] * e2;
        acc[13] += ssph[b][13] * e2;
        acc[14] += ssph[b][14] * e2;
        __syncthreads();
        pv0 = n0; pv1 = n1; pv2 = n2; pv3 = n3;
        av = an;
    }

    // final flush: cur gets acc, remaining atoms bias-only
#pragma unroll
    for (int m = 0; m < 15; m++)
        out[((size_t)cur * 15 + m) * 128 + c] = acc[m] + bo;
    for (int a = cur + 1; a < a0 + APB; a++)
#pragma unroll
        for (int m = 0; m < 15; m++)
            out[((size_t)a * 15 + m) * 128 + c] = bo;
}

// ---------------------------------------------------------------------------
extern "C" void kernel_launch(void* const* d_in, const int* in_sizes, int n_in,
                              void* d_out, int out_size)
{
    const float* x     = (const float*)d_in[0];
    const float* rbf   = (const float*)d_in[1];
    const float* sph   = (const float*)d_in[2];
    const float* phi   = (const float*)d_in[3];
    const int*   idx_i = (const int*)  d_in[4];
    const int*   idx_j = (const int*)  d_in[5];
    const float* pmask = (const float*)d_in[6];
    const float* WQ    = (const float*)d_in[7];
    const float* WK    = (const float*)d_in[8];
    const float* W_in  = (const float*)d_in[9];
    const float* b_in  = (const float*)d_in[10];
    const float* Wf1   = (const float*)d_in[11];
    const float* bf1   = (const float*)d_in[12];
    const float* Wf2   = (const float*)d_in[13];
    const float* bf2   = (const float*)d_in[14];
    const float* W_out = (const float*)d_in[15];
    const float* b_out = (const float*)d_in[16];
    float* out = (float*)d_out;

    // One dummy: ncu capture (2 harness launches + skip) lands on agg_kernel.
    dummy_kernel<<<1, 32>>>();
    prep_kernel<<<(NATOMS + 31) / 32, 256>>>(x, W_in, b_in, WQ, WK, W_out);
    alpha_kernel<<<296, 256>>>(rbf, phi, pmask, idx_i, idx_j,
                               Wf1, bf1, Wf2, bf2, sph);
    agg_kernel<<<NATOMS / APB, 128>>>(idx_i, idx_j, b_out, out);
}